// round 3
// baseline (speedup 1.0000x reference)
#include <cuda_runtime.h>
#include <math.h>

#define NB   8
#define NDIM 64
#define NH   128
#define NW   128
#define NPIX (NH * NW)     // 16384
#define NC2  256
#define NHID 128

// Scratch (device-global: allocation in kernel_launch is forbidden)
__device__ float g_u[(size_t)NB * NC2 * NPIX];    // project_in output  (134 MB)
__device__ float g_g[(size_t)NB * NHID * NPIX];   // gated output       (67 MB)

// ---- packed fp32x2 helpers (Blackwell FFMA2 path; ptxas never auto-fuses) ----
__device__ __forceinline__ unsigned long long pk2(float lo, float hi) {
    unsigned long long r;
    asm("mov.b64 %0, {%1, %2};" : "=l"(r) : "f"(lo), "f"(hi));
    return r;
}
__device__ __forceinline__ void fma2(unsigned long long& d, unsigned long long a,
                                     unsigned long long b) {
    asm("fma.rn.f32x2 %0, %1, %2, %0;" : "+l"(d) : "l"(a), "l"(b));
}
__device__ __forceinline__ float2 up2(unsigned long long v) {
    float2 f;
    asm("mov.b64 {%0, %1}, %2;" : "=f"(f.x), "=f"(f.y) : "l"(v));
    return f;
}

// ============================================================================
// K1: project_in  u[b][c][p] = sum_k W_in[c][k] * x[b][k][p]
// Block tile: 64 channels x 128 pixels, K=64. 256 threads.
// Thread tile: 8 channels (4 packed pairs) x 4 pixels.
// ============================================================================
__global__ __launch_bounds__(256, 2)
void k_proj_in(const float* __restrict__ x, const float* __restrict__ W_in) {
    __shared__ float Wt[64 * 64];    // [k][c_local]  (transposed)
    __shared__ float Xs[64 * 128];   // [k][p_local]

    const int p0  = blockIdx.x * 128;
    const int c0  = blockIdx.y * 64;
    const int b   = blockIdx.z;
    const int tid = threadIdx.x;

    for (int l = tid; l < 64 * 64; l += 256) {
        int c = l >> 6, k = l & 63;
        Wt[k * 64 + c] = W_in[(c0 + c) * 64 + k];
    }
    const float* xb = x + ((size_t)b * NDIM) * NPIX + p0;
    for (int l = tid; l < 64 * 32; l += 256) {
        int k = l >> 5, p4 = l & 31;
        ((float4*)(Xs + k * 128))[p4] = ((const float4*)(xb + (size_t)k * NPIX))[p4];
    }
    __syncthreads();

    const int pg = (tid & 31) * 4;   // pixel offset in tile
    const int cg = (tid >> 5) * 8;   // channel offset in tile

    unsigned long long acc[4][4];
#pragma unroll
    for (int i = 0; i < 4; i++)
#pragma unroll
        for (int j = 0; j < 4; j++) acc[i][j] = 0ULL;

#pragma unroll 4
    for (int k = 0; k < 64; k++) {
        const unsigned long long* wp =
            (const unsigned long long*)(Wt + k * 64 + cg);   // 8B-aligned
        unsigned long long w0 = wp[0], w1 = wp[1], w2 = wp[2], w3 = wp[3];
        float4 xv = *(const float4*)(Xs + k * 128 + pg);
        unsigned long long x0 = pk2(xv.x, xv.x);
        unsigned long long x1 = pk2(xv.y, xv.y);
        unsigned long long x2 = pk2(xv.z, xv.z);
        unsigned long long x3 = pk2(xv.w, xv.w);
        fma2(acc[0][0], w0, x0); fma2(acc[0][1], w0, x1);
        fma2(acc[0][2], w0, x2); fma2(acc[0][3], w0, x3);
        fma2(acc[1][0], w1, x0); fma2(acc[1][1], w1, x1);
        fma2(acc[1][2], w1, x2); fma2(acc[1][3], w1, x3);
        fma2(acc[2][0], w2, x0); fma2(acc[2][1], w2, x1);
        fma2(acc[2][2], w2, x2); fma2(acc[2][3], w2, x3);
        fma2(acc[3][0], w3, x0); fma2(acc[3][1], w3, x1);
        fma2(acc[3][2], w3, x2); fma2(acc[3][3], w3, x3);
    }

    float* ub = g_u + (((size_t)b * NC2 + c0 + cg) * NPIX) + p0 + pg;
#pragma unroll
    for (int cp = 0; cp < 4; cp++) {
        float2 v0 = up2(acc[cp][0]), v1 = up2(acc[cp][1]);
        float2 v2 = up2(acc[cp][2]), v3 = up2(acc[cp][3]);
        float4 lo = make_float4(v0.x, v1.x, v2.x, v3.x);
        float4 hi = make_float4(v0.y, v1.y, v2.y, v3.y);
        *(float4*)(ub + (size_t)(2 * cp) * NPIX)     = lo;
        *(float4*)(ub + (size_t)(2 * cp + 1) * NPIX) = hi;
    }
}

// ============================================================================
// K2: dynamic depthwise 3x3 (SAME, cross-correlation) + exact-erf GELU gate
// g[b][c][p] = gelu(dw(u[b][c])) * dw(u[b][c+128])
// Block: one (b,c), 16 output rows. 256 threads x 8 pixels.
// ============================================================================
__global__ __launch_bounds__(256)
void k_dwgate(const float* __restrict__ gen, const float* __restrict__ dwk,
              const float* __restrict__ lam) {
    __shared__ float s1[18 * 128];
    __shared__ float s2[18 * 128];

    const int r0  = blockIdx.x * 16;
    const int c   = blockIdx.y;
    const int b   = blockIdx.z;
    const int tid = threadIdx.x;

    float kk1[9], kk2[9];
    const float l1 = lam[c], l2 = lam[c + 128];
#pragma unroll
    for (int j = 0; j < 9; j++) {
        kk1[j] = dwk[c * 9 + j]          + l1 * gen[((size_t)b * NC2 + c) * 9 + j];
        kk2[j] = dwk[(c + 128) * 9 + j]  + l2 * gen[((size_t)b * NC2 + c + 128) * 9 + j];
    }

    const float* u1 = g_u + ((size_t)b * NC2 + c) * NPIX;
    const float* u2 = u1 + (size_t)NHID * NPIX;

    // stage rows r0-1 .. r0+16 (18 rows x 128), zero-fill out-of-range
    for (int l = tid; l < 18 * 32; l += 256) {
        int rr = l >> 5, p4 = l & 31;
        int gy = r0 + rr - 1;
        float4 a  = make_float4(0.f, 0.f, 0.f, 0.f);
        float4 bb = a;
        if (gy >= 0 && gy < NH) {
            a  = ((const float4*)(u1 + (size_t)gy * NW))[p4];
            bb = ((const float4*)(u2 + (size_t)gy * NW))[p4];
        }
        ((float4*)(s1 + rr * 128))[p4] = a;
        ((float4*)(s2 + rr * 128))[p4] = bb;
    }
    __syncthreads();

    float* gp = g_g + ((size_t)b * NHID + c) * NPIX + (size_t)r0 * NW;
#pragma unroll
    for (int i = 0; i < 8; i++) {
        int lp = tid + i * 256;     // 0..2047
        int lr = lp >> 7;           // local output row 0..15
        int xx = lp & 127;
        float a1 = 0.f, a2 = 0.f;
#pragma unroll
        for (int ky = 0; ky < 3; ky++) {
            const float* r1 = s1 + (lr + ky) * 128;
            const float* r2 = s2 + (lr + ky) * 128;
#pragma unroll
            for (int kx = 0; kx < 3; kx++) {
                int xc = xx + kx - 1;
                if (xc >= 0 && xc < NW) {
                    a1 += kk1[ky * 3 + kx] * r1[xc];
                    a2 += kk2[ky * 3 + kx] * r2[xc];
                }
            }
        }
        float ge = 0.5f * a1 * (1.0f + erff(a1 * 0.7071067811865475f));
        gp[lp] = ge * a2;
    }
}

// ============================================================================
// K3: project_out  out[b][o][p] = sum_c W_out[o][c] * g[b][c][p]
// Block tile: 64 out-channels x 128 pixels, K=128. 256 threads.
// Dynamic smem: Wt[128][64] + Xs[128][128] = 96 KB.
// ============================================================================
__global__ __launch_bounds__(256, 2)
void k_proj_out(const float* __restrict__ W_out, float* __restrict__ out) {
    extern __shared__ float sm[];
    float* Wt = sm;               // [k=128][o=64]
    float* Xs = sm + 128 * 64;    // [k=128][p=128]

    const int p0  = blockIdx.x * 128;
    const int b   = blockIdx.y;
    const int tid = threadIdx.x;

    for (int l = tid; l < 64 * 128; l += 256) {
        int o = l >> 7, k = l & 127;
        Wt[k * 64 + o] = W_out[o * 128 + k];
    }
    const float* gb = g_g + (size_t)b * NHID * NPIX + p0;
    for (int l = tid; l < 128 * 32; l += 256) {
        int k = l >> 5, p4 = l & 31;
        ((float4*)(Xs + k * 128))[p4] = ((const float4*)(gb + (size_t)k * NPIX))[p4];
    }
    __syncthreads();

    const int pg = (tid & 31) * 4;
    const int og = (tid >> 5) * 8;

    unsigned long long acc[4][4];
#pragma unroll
    for (int i = 0; i < 4; i++)
#pragma unroll
        for (int j = 0; j < 4; j++) acc[i][j] = 0ULL;

#pragma unroll 4
    for (int k = 0; k < 128; k++) {
        const unsigned long long* wp =
            (const unsigned long long*)(Wt + k * 64 + og);
        unsigned long long w0 = wp[0], w1 = wp[1], w2 = wp[2], w3 = wp[3];
        float4 xv = *(const float4*)(Xs + k * 128 + pg);
        unsigned long long x0 = pk2(xv.x, xv.x);
        unsigned long long x1 = pk2(xv.y, xv.y);
        unsigned long long x2 = pk2(xv.z, xv.z);
        unsigned long long x3 = pk2(xv.w, xv.w);
        fma2(acc[0][0], w0, x0); fma2(acc[0][1], w0, x1);
        fma2(acc[0][2], w0, x2); fma2(acc[0][3], w0, x3);
        fma2(acc[1][0], w1, x0); fma2(acc[1][1], w1, x1);
        fma2(acc[1][2], w1, x2); fma2(acc[1][3], w1, x3);
        fma2(acc[2][0], w2, x0); fma2(acc[2][1], w2, x1);
        fma2(acc[2][2], w2, x2); fma2(acc[2][3], w2, x3);
        fma2(acc[3][0], w3, x0); fma2(acc[3][1], w3, x1);
        fma2(acc[3][2], w3, x2); fma2(acc[3][3], w3, x3);
    }

    float* ob = out + (((size_t)b * NDIM + og) * NPIX) + p0 + pg;
#pragma unroll
    for (int cp = 0; cp < 4; cp++) {
        float2 v0 = up2(acc[cp][0]), v1 = up2(acc[cp][1]);
        float2 v2 = up2(acc[cp][2]), v3 = up2(acc[cp][3]);
        float4 lo = make_float4(v0.x, v1.x, v2.x, v3.x);
        float4 hi = make_float4(v0.y, v1.y, v2.y, v3.y);
        *(float4*)(ob + (size_t)(2 * cp) * NPIX)     = lo;
        *(float4*)(ob + (size_t)(2 * cp + 1) * NPIX) = hi;
    }
}

// ============================================================================
extern "C" void kernel_launch(void* const* d_in, const int* in_sizes, int n_in,
                              void* d_out, int out_size) {
    const float* x     = (const float*)d_in[0];   // (8,64,128,128)
    const float* gen   = (const float*)d_in[1];   // (8,256,1,3,3)
    const float* W_in  = (const float*)d_in[2];   // (256,64)
    const float* dwk   = (const float*)d_in[3];   // (1,256,1,3,3)
    const float* lam   = (const float*)d_in[4];   // (1,256,1,1,1)
    const float* W_out = (const float*)d_in[5];   // (64,128)
    float* out = (float*)d_out;                   // (8,64,128,128)

    k_proj_in<<<dim3(NPIX / 128, NC2 / 64, NB), 256>>>(x, W_in);
    k_dwgate<<<dim3(NH / 16, NHID, NB), 256>>>(gen, dwk, lam);

    const int k3_smem = (128 * 64 + 128 * 128) * (int)sizeof(float);  // 96 KB
    cudaFuncSetAttribute(k_proj_out, cudaFuncAttributeMaxDynamicSharedMemorySize,
                         k3_smem);
    k_proj_out<<<dim3(NPIX / 128, NB), 256, k3_smem>>>(W_out, out);
}

// round 4
// speedup vs baseline: 1.2251x; 1.2251x over previous
#include <cuda_runtime.h>
#include <math.h>

#define NB   8
#define NDIM 64
#define NH   128
#define NW   128
#define NPIX (NH * NW)     // 16384
#define NC2  256
#define NHID 128

// Global scratch (no allocation allowed in kernel_launch)
__device__ float g_u[(size_t)NB * NC2 * NPIX];    // project_in output  (134 MB)
__device__ float g_g[(size_t)NB * NHID * NPIX];   // gated output       (67 MB)
__device__ float g_Wd1[4 * 64 * 128];             // W_in  dup: [tile][k][2c]  128 KB
__device__ float g_Wd3[128 * 128];                // W_out dup: [k][2o]        64 KB

// ---- packed fp32x2 helpers ----
__device__ __forceinline__ void fma2(unsigned long long& d, unsigned long long a,
                                     unsigned long long b) {
    asm("fma.rn.f32x2 %0, %1, %2, %0;" : "+l"(d) : "l"(a), "l"(b));
}
__device__ __forceinline__ float2 up2(unsigned long long v) {
    float2 f;
    asm("mov.b64 {%0, %1}, %2;" : "=f"(f.x), "=f"(f.y) : "l"(v));
    return f;
}

// ============================================================================
// K0: duplicate weights into global scratch (runs once per launch, ~2us)
//   g_Wd1[tile][k][2c] = g_Wd1[tile][k][2c+1] = W_in[(64*tile+c)*64 + k]
//   g_Wd3[k][2o]       = g_Wd3[k][2o+1]       = W_out[o*128 + k]
// ============================================================================
__global__ void k_prep(const float* __restrict__ W_in,
                       const float* __restrict__ W_out) {
    int t = blockIdx.x * 256 + threadIdx.x;
    if (t < 4 * 64 * 64) {
        int tile = t >> 12, c = (t >> 6) & 63, k = t & 63;
        float w = W_in[(tile * 64 + c) * 64 + k];
        float2* p = (float2*)(g_Wd1 + (size_t)(tile * 64 + k) * 128 + 2 * c);
        *p = make_float2(w, w);
    }
    if (t < 64 * 128) {
        int o = t >> 7, k = t & 127;
        float w = W_out[o * 128 + k];
        float2* p = (float2*)(g_Wd3 + (size_t)k * 128 + 2 * o);
        *p = make_float2(w, w);
    }
}

// ============================================================================
// K1: project_in  u[b][c][p] = sum_k W_in[c][k] * x[b][k][p]
// Tile: 64 ch x 128 px, K=64. 256 threads, thread tile 8 ch x 4 px.
// Weights pre-duplicated: acc packs PIXEL pairs, w broadcast-packed (w,w).
// Per k: 4 LDS.128(bcast w) + 1 LDS.128(x) + 16 FFMA2. No packing MOVs.
// smem 64KB -> 3 blocks/SM.
// ============================================================================
__global__ __launch_bounds__(256, 3)
void k_proj_in(const float* __restrict__ x) {
    extern __shared__ float sm[];
    float* Wd = sm;           // [k=64][128]  (dup channels)
    float* Xs = sm + 8192;    // [k=64][128]  (pixels)

    const int p0  = blockIdx.x * 128;
    const int ct  = blockIdx.y;           // channel tile (64 ch)
    const int b   = blockIdx.z;
    const int tid = threadIdx.x;

    // coalesced float4 copies, conflict-free STS
    const float4* ws = (const float4*)(g_Wd1 + (size_t)ct * 8192);
    for (int l = tid; l < 2048; l += 256) ((float4*)Wd)[l] = ws[l];
    const float* xb = x + (size_t)b * NDIM * NPIX + p0;
    for (int l = tid; l < 64 * 32; l += 256) {
        int k = l >> 5, p4 = l & 31;
        ((float4*)(Xs + k * 128))[p4] = ((const float4*)(xb + (size_t)k * NPIX))[p4];
    }
    __syncthreads();

    const int pg = (tid & 31) * 4;   // pixel offset
    const int cg = (tid >> 5) * 8;   // channel offset

    unsigned long long acc[8][2];
#pragma unroll
    for (int i = 0; i < 8; i++) { acc[i][0] = 0ULL; acc[i][1] = 0ULL; }

#pragma unroll 8
    for (int k = 0; k < 64; k++) {
        const ulonglong2* wp = (const ulonglong2*)(Wd + k * 128 + 2 * cg);
        ulonglong2 w01 = wp[0], w23 = wp[1], w45 = wp[2], w67 = wp[3];
        ulonglong2 xv  = *(const ulonglong2*)(Xs + k * 128 + pg);
        fma2(acc[0][0], w01.x, xv.x); fma2(acc[0][1], w01.x, xv.y);
        fma2(acc[1][0], w01.y, xv.x); fma2(acc[1][1], w01.y, xv.y);
        fma2(acc[2][0], w23.x, xv.x); fma2(acc[2][1], w23.x, xv.y);
        fma2(acc[3][0], w23.y, xv.x); fma2(acc[3][1], w23.y, xv.y);
        fma2(acc[4][0], w45.x, xv.x); fma2(acc[4][1], w45.x, xv.y);
        fma2(acc[5][0], w45.y, xv.x); fma2(acc[5][1], w45.y, xv.y);
        fma2(acc[6][0], w67.x, xv.x); fma2(acc[6][1], w67.x, xv.y);
        fma2(acc[7][0], w67.y, xv.x); fma2(acc[7][1], w67.y, xv.y);
    }

    float* ub = g_u + ((size_t)(b * NC2 + ct * 64 + cg)) * NPIX + p0 + pg;
#pragma unroll
    for (int c = 0; c < 8; c++) {
        float2 lo = up2(acc[c][0]), hi = up2(acc[c][1]);
        *(float4*)(ub + (size_t)c * NPIX) = make_float4(lo.x, lo.y, hi.x, hi.y);
    }
}

// ============================================================================
// K2: dynamic depthwise 3x3 (SAME) + exact-erf GELU gate
// Padded smem rows (stride 136, data at cols 4..131, halo 3/132 zeroed)
// -> no per-tap bounds checks.
// ============================================================================
#define SROW 136
__global__ __launch_bounds__(256)
void k_dwgate(const float* __restrict__ gen, const float* __restrict__ dwk,
              const float* __restrict__ lam) {
    __shared__ float s1[18 * SROW];
    __shared__ float s2[18 * SROW];

    const int r0  = blockIdx.x * 16;
    const int c   = blockIdx.y;
    const int b   = blockIdx.z;
    const int tid = threadIdx.x;

    float kk1[9], kk2[9];
    const float l1 = lam[c], l2 = lam[c + 128];
#pragma unroll
    for (int j = 0; j < 9; j++) {
        kk1[j] = dwk[c * 9 + j]         + l1 * gen[((size_t)b * NC2 + c) * 9 + j];
        kk2[j] = dwk[(c + 128) * 9 + j] + l2 * gen[((size_t)b * NC2 + c + 128) * 9 + j];
    }

    const float* u1 = g_u + ((size_t)b * NC2 + c) * NPIX;
    const float* u2 = u1 + (size_t)NHID * NPIX;

    for (int l = tid; l < 18 * 32; l += 256) {
        int rr = l >> 5, p4 = l & 31;
        int gy = r0 + rr - 1;
        float4 a  = make_float4(0.f, 0.f, 0.f, 0.f);
        float4 bb = a;
        if (gy >= 0 && gy < NH) {
            a  = ((const float4*)(u1 + (size_t)gy * NW))[p4];
            bb = ((const float4*)(u2 + (size_t)gy * NW))[p4];
        }
        ((float4*)(s1 + rr * SROW + 4))[p4] = a;
        ((float4*)(s2 + rr * SROW + 4))[p4] = bb;
    }
    if (tid < 36) {   // zero halo columns (x=-1 -> col 3, x=128 -> col 132)
        int rr = tid >> 1, col = (tid & 1) ? 132 : 3;
        s1[rr * SROW + col] = 0.f;
        s2[rr * SROW + col] = 0.f;
    }
    __syncthreads();

    float* gp = g_g + ((size_t)b * NHID + c) * NPIX + (size_t)r0 * NW;
#pragma unroll
    for (int i = 0; i < 8; i++) {
        int lp = tid + i * 256;
        int lr = lp >> 7;
        int xx = lp & 127;
        float a1 = 0.f, a2 = 0.f;
#pragma unroll
        for (int ky = 0; ky < 3; ky++) {
            const float* r1 = s1 + (lr + ky) * SROW + 4 + xx;
            const float* r2 = s2 + (lr + ky) * SROW + 4 + xx;
            a1 += kk1[ky * 3 + 0] * r1[-1] + kk1[ky * 3 + 1] * r1[0] + kk1[ky * 3 + 2] * r1[1];
            a2 += kk2[ky * 3 + 0] * r2[-1] + kk2[ky * 3 + 1] * r2[0] + kk2[ky * 3 + 2] * r2[1];
        }
        float ge = 0.5f * a1 * (1.0f + erff(a1 * 0.7071067811865475f));
        gp[lp] = ge * a2;
    }
}

// ============================================================================
// K3: project_out  out[b][o][p] = sum_c W_out[o][c] * g[b][c][p]
// Tile: 64 out x 128 px, K=128 in two 64-chunks (Wd+Xs reloaded per chunk).
// Same FFMA2 inner loop. smem 64KB -> 3 blocks/SM.
// ============================================================================
__global__ __launch_bounds__(256, 3)
void k_proj_out(float* __restrict__ out) {
    extern __shared__ float sm[];
    float* Wd = sm;           // [k=64][128] (dup out-channels, per chunk)
    float* Xs = sm + 8192;    // [k=64][128]

    const int p0  = blockIdx.x * 128;
    const int b   = blockIdx.y;
    const int tid = threadIdx.x;

    const int pg = (tid & 31) * 4;
    const int og = (tid >> 5) * 8;

    unsigned long long acc[8][2];
#pragma unroll
    for (int i = 0; i < 8; i++) { acc[i][0] = 0ULL; acc[i][1] = 0ULL; }

    for (int kc = 0; kc < 2; kc++) {
        const float4* ws = (const float4*)(g_Wd3 + (size_t)kc * 8192);
        for (int l = tid; l < 2048; l += 256) ((float4*)Wd)[l] = ws[l];
        const float* gb = g_g + ((size_t)b * NHID + kc * 64) * NPIX + p0;
        for (int l = tid; l < 64 * 32; l += 256) {
            int k = l >> 5, p4 = l & 31;
            ((float4*)(Xs + k * 128))[p4] =
                ((const float4*)(gb + (size_t)k * NPIX))[p4];
        }
        __syncthreads();

#pragma unroll 8
        for (int k = 0; k < 64; k++) {
            const ulonglong2* wp = (const ulonglong2*)(Wd + k * 128 + 2 * og);
            ulonglong2 w01 = wp[0], w23 = wp[1], w45 = wp[2], w67 = wp[3];
            ulonglong2 xv  = *(const ulonglong2*)(Xs + k * 128 + pg);
            fma2(acc[0][0], w01.x, xv.x); fma2(acc[0][1], w01.x, xv.y);
            fma2(acc[1][0], w01.y, xv.x); fma2(acc[1][1], w01.y, xv.y);
            fma2(acc[2][0], w23.x, xv.x); fma2(acc[2][1], w23.x, xv.y);
            fma2(acc[3][0], w23.y, xv.x); fma2(acc[3][1], w23.y, xv.y);
            fma2(acc[4][0], w45.x, xv.x); fma2(acc[4][1], w45.x, xv.y);
            fma2(acc[5][0], w45.y, xv.x); fma2(acc[5][1], w45.y, xv.y);
            fma2(acc[6][0], w67.x, xv.x); fma2(acc[6][1], w67.x, xv.y);
            fma2(acc[7][0], w67.y, xv.x); fma2(acc[7][1], w67.y, xv.y);
        }
        __syncthreads();
    }

    float* ob = out + ((size_t)(b * NDIM + og)) * NPIX + p0 + pg;
#pragma unroll
    for (int o = 0; o < 8; o++) {
        float2 lo = up2(acc[o][0]), hi = up2(acc[o][1]);
        *(float4*)(ob + (size_t)o * NPIX) = make_float4(lo.x, lo.y, hi.x, hi.y);
    }
}

// ============================================================================
extern "C" void kernel_launch(void* const* d_in, const int* in_sizes, int n_in,
                              void* d_out, int out_size) {
    const float* x     = (const float*)d_in[0];   // (8,64,128,128)
    const float* gen   = (const float*)d_in[1];   // (8,256,1,3,3)
    const float* W_in  = (const float*)d_in[2];   // (256,64)
    const float* dwk   = (const float*)d_in[3];   // (1,256,1,3,3)
    const float* lam   = (const float*)d_in[4];   // (1,256,1,1,1)
    const float* W_out = (const float*)d_in[5];   // (64,128)
    float* out = (float*)d_out;                   // (8,64,128,128)

    const int smem = 64 * 1024;
    static int attr_done = 0;
    if (!attr_done) {
        cudaFuncSetAttribute(k_proj_in,  cudaFuncAttributeMaxDynamicSharedMemorySize, smem);
        cudaFuncSetAttribute(k_proj_out, cudaFuncAttributeMaxDynamicSharedMemorySize, smem);
        attr_done = 1;
    }

    k_prep<<<64, 256>>>(W_in, W_out);
    k_proj_in<<<dim3(NPIX / 128, NC2 / 64, NB), 256, smem>>>(x);
    k_dwgate<<<dim3(NH / 16, NHID, NB), 256>>>(gen, dwk, lam);
    k_proj_out<<<dim3(NPIX / 128, NB), 256, smem>>>(out);
}